// round 5
// baseline (speedup 1.0000x reference)
#include <cuda_runtime.h>
#include <cuda_bf16.h>
#include <cstdint>

// ---------------------------------------------------------------------------
// Problem constants
// ---------------------------------------------------------------------------
#define BBATCH 16
#define TSTEPS 32
#define CCH    512            // hidden channels
#define PPOS   1024           // 32*32 spatial positions
#define OO     2048           // 4 * CCH gate rows
#define KAUG   1536           // augmented K: [W_hi|W_lo|W_hi] x [h_hi|h_hi|h_lo]
#define KC     64             // K per pipeline chunk (128B bf16 rows)
#define NCHUNK (KAUG / KC)    // 24
#define NCH    64             // channels per CTA
#define MP     128            // spatial positions per CTA (M)

// ---------------------------------------------------------------------------
// Persistent state (ping-pong h across timesteps to avoid intra-launch races)
// ---------------------------------------------------------------------------
__device__ __align__(16) __nv_bfloat16 g_haug[2][(size_t)BBATCH * PPOS * KAUG]; // 2 x 50 MB
__device__ __align__(16) float         g_cT[(size_t)BBATCH * PPOS * CCH];       // 33 MB
__device__ __align__(16) __nv_bfloat16 g_waug[(size_t)OO * KAUG];               // 6.3 MB

// ---------------------------------------------------------------------------
// Helpers (all compute_80-level PTX: cp.async, ldmatrix, mma.sync)
// ---------------------------------------------------------------------------
__device__ __forceinline__ uint32_t smem_u32(const void* p) {
    uint32_t a;
    asm("{ .reg .u64 t; cvta.to.shared.u64 t, %1; cvt.u32.u64 %0, t; }"
        : "=r"(a) : "l"(p));
    return a;
}

#define SWZ128(o) ((o) ^ (((o) >> 3) & 0x70))

__device__ __forceinline__ void cp_async16(uint32_t dst, const void* src) {
    asm volatile("cp.async.cg.shared.global [%0], [%1], 16;" :: "r"(dst), "l"(src));
}
#define CP_COMMIT()   asm volatile("cp.async.commit_group;" ::: "memory")
#define CP_WAIT(n)    asm volatile("cp.async.wait_group %0;" :: "n"(n) : "memory")

__device__ __forceinline__ void ldsm_x4(uint32_t* r, uint32_t addr) {
    asm volatile("ldmatrix.sync.aligned.m8n8.x4.shared.b16 {%0,%1,%2,%3}, [%4];"
        : "=r"(r[0]), "=r"(r[1]), "=r"(r[2]), "=r"(r[3]) : "r"(addr));
}

__device__ __forceinline__ void mma16816(float* d, const uint32_t* a, const uint32_t* b) {
    asm volatile(
        "mma.sync.aligned.m16n8k16.row.col.f32.bf16.bf16.f32 "
        "{%0,%1,%2,%3}, {%4,%5,%6,%7}, {%8,%9}, {%0,%1,%2,%3};"
        : "+f"(d[0]), "+f"(d[1]), "+f"(d[2]), "+f"(d[3])
        : "r"(a[0]), "r"(a[1]), "r"(a[2]), "r"(a[3]), "r"(b[0]), "r"(b[1]));
}

__device__ __forceinline__ float sigf(float v) { return 1.0f / (1.0f + __expf(-v)); }
__device__ __forceinline__ float tanh_f(float v) { return 2.0f * sigf(2.0f * v) - 1.0f; }

// ---------------------------------------------------------------------------
// Init: zero h buffer 0 and cT
// ---------------------------------------------------------------------------
__global__ void init_state_kernel() {
    const size_t NH = (size_t)BBATCH * PPOS * KAUG / 2;
    const size_t NC = (size_t)BBATCH * PPOS * CCH;
    size_t i = (size_t)blockIdx.x * 256 + threadIdx.x;
    if (i < NH) ((uint32_t*)g_haug[0])[i] = 0u;
    if (i < NC) g_cT[i] = 0.0f;
}

// Build W_aug = [W_hi | W_lo | W_hi] per gate row (from W[:,1:] of the 1x1 conv)
__global__ void build_waug_kernel(const float* __restrict__ W) {
    int i = blockIdx.x * 256 + threadIdx.x;
    if (i >= OO * CCH) return;
    int o = i >> 9, c = i & 511;
    float w = W[(size_t)o * 513 + 1 + c];
    __nv_bfloat16 hi = __float2bfloat16_rn(w);
    __nv_bfloat16 lo = __float2bfloat16_rn(w - __bfloat162float(hi));
    __nv_bfloat16* row = g_waug + (size_t)o * KAUG;
    row[c] = hi; row[512 + c] = lo; row[1024 + c] = hi;
}

// ---------------------------------------------------------------------------
// Fused gates-GEMM (mma.sync bf16, split precision) + LSTM pointwise epilogue.
// Grid: (8 p-tiles, 8 ch-tiles, 16 b). 256 threads = 8 warps (2 m x 4 n).
// Warp tile 64(m) x 64(n); CTA 128 x 256 (4 gates x 64 ch); K = 1536.
// ---------------------------------------------------------------------------
#define STAGE_SZ   49152                  // A 16KB + B 32KB
#define SM_A(s)    ((s) * STAGE_SZ)
#define SM_B(s)    ((s) * STAGE_SZ + 16384)
#define SM_W0      98304
#define SM_BIAS    99328
#define SMEM_TOTAL (100352 + 1024)        // + alignment slack

__global__ __launch_bounds__(256) void gemm_lstm_kernel(
    const float* __restrict__ W,      // [2048][513]
    const float* __restrict__ bconv,  // [2048]
    const float* __restrict__ x,      // [B][T][1024]
    int t)
{
    extern __shared__ char smem_raw[];
    const uint32_t sbase0 = smem_u32(smem_raw);
    const uint32_t abase  = (sbase0 + 1023) & ~1023u;   // 1024-aligned base
    char* smem = smem_raw + (abase - sbase0);

    const int tid  = threadIdx.x;
    const int wid  = tid >> 5;
    const int lane = tid & 31;
    const int mw   = wid >> 2;          // 0..1  (m warp)
    const int gate = wid & 3;           // 0..3  (n warp == gate)

    const int b   = blockIdx.z;
    const int ch0 = blockIdx.y * NCH;
    const int p0  = blockIdx.x * MP;

    const __nv_bfloat16* __restrict__ hrd = g_haug[t & 1];
    __nv_bfloat16* __restrict__ hwr       = g_haug[(t + 1) & 1];
    const __nv_bfloat16* __restrict__ hb  = hrd + (size_t)b * PPOS * KAUG;

    // stage loader: chunk c -> stage s
    auto load_stage = [&](int c, int s) {
        const int k0 = c * KC;
        const uint32_t da = abase + SM_A(s);
#pragma unroll
        for (int i = 0; i < 4; i++) {                       // A: 1024 x 16B
            int idx = tid + i * 256;
            int r = idx >> 3, c8 = idx & 7;
            cp_async16(da + SWZ128(r * 128 + c8 * 16),
                       hb + (size_t)(p0 + r) * KAUG + k0 + c8 * 8);
        }
        const uint32_t db = abase + SM_B(s);
#pragma unroll
        for (int i = 0; i < 8; i++) {                       // B: 2048 x 16B
            int idx = tid + i * 256;
            int g = idx >> 9, rr = (idx >> 3) & 63, c8 = idx & 7;
            cp_async16(db + SWZ128((g * 64 + rr) * 128 + c8 * 16),
                       g_waug + (size_t)(g * 512 + ch0 + rr) * KAUG + k0 + c8 * 8);
        }
        CP_COMMIT();
    };

    // stage w0 / bias (epilogue constants) while pipeline warms
    load_stage(0, 0);
    load_stage(1, 1);
    {
        float* sW0   = (float*)(smem + SM_W0);
        float* sBias = (float*)(smem + SM_BIAS);
        if (tid < 256) {
            int o = (tid >> 6) * 512 + ch0 + (tid & 63);
            sW0[tid]   = W[(size_t)o * 513];
            sBias[tid] = bconv[o];
        }
    }

    float acc[4][8][4];
#pragma unroll
    for (int mt = 0; mt < 4; mt++)
#pragma unroll
        for (int nt = 0; nt < 8; nt++)
#pragma unroll
            for (int e = 0; e < 4; e++) acc[mt][nt][e] = 0.0f;

    // precomputed ldmatrix row-byte offsets (swizzle applied at use)
    uint32_t rA[4], rB[4];
#pragma unroll
    for (int mt = 0; mt < 4; mt++)
        rA[mt] = (uint32_t)(mw * 64 + mt * 16 + (lane & 15)) * 128;
#pragma unroll
    for (int np = 0; np < 4; np++)
        rB[np] = (uint32_t)(gate * 64 + np * 16 + (lane & 7) + ((lane >> 4) << 3)) * 128;
    const uint32_t kA = (lane >> 4);            // A k-half select
    const uint32_t kB = ((lane >> 3) & 1);      // B k-half select

    for (int c = 0; c < NCHUNK; c++) {
        const int s = c & 1;
        if (c == NCHUNK - 1) CP_WAIT(0); else CP_WAIT(1);
        __syncthreads();

        const uint32_t Ab = abase + SM_A(s);
        const uint32_t Bb = abase + SM_B(s);
#pragma unroll
        for (int kk = 0; kk < 4; kk++) {
            uint32_t af[4][4], bf[4][4];
#pragma unroll
            for (int mt = 0; mt < 4; mt++)
                ldsm_x4(af[mt], Ab + SWZ128(rA[mt] + (kk * 2 + kA) * 16));
#pragma unroll
            for (int np = 0; np < 4; np++)
                ldsm_x4(bf[np], Bb + SWZ128(rB[np] + (kk * 2 + kB) * 16));
#pragma unroll
            for (int mt = 0; mt < 4; mt++)
#pragma unroll
                for (int nt = 0; nt < 8; nt++)
                    mma16816(acc[mt][nt], af[mt], &bf[nt >> 1][(nt & 1) * 2]);
        }
        __syncthreads();
        if (c + 2 < NCHUNK) load_stage(c + 2, s);
    }

    // ---- epilogue: 4 chunks of 16 ch via SMEM (stride-68 pad) ----
    float* sEpi  = (float*)smem;                 // 128*68*4 = 34816 B (stage0 done)
    float* sW0   = (float*)(smem + SM_W0);
    float* sBias = (float*)(smem + SM_BIAS);

    const int p_l  = tid & 127;
    const int half = tid >> 7;                   // 0/1 -> 8-ch sub-slab
    const int p    = p0 + p_l;
    const float xv = x[((size_t)b * TSTEPS + t) * PPOS + p];
    float* __restrict__ cT = g_cT + ((size_t)b * PPOS + p) * CCH + ch0;
    __nv_bfloat16* __restrict__ hrow = hwr + ((size_t)b * PPOS + p) * KAUG;

#pragma unroll 1
    for (int q = 0; q < 4; q++) {
        __syncthreads();
        // scatter this chunk's accumulators into SMEM
#pragma unroll
        for (int mt = 0; mt < 4; mt++) {
#pragma unroll
            for (int j = 0; j < 2; j++) {
                const int nt  = q * 2 + j;
                const int m   = mw * 64 + mt * 16 + (lane >> 2);
                const int chl = j * 8 + (lane & 3) * 2;
                float* d0 = sEpi + (size_t)m * 68 + gate * 16 + chl;
                d0[0] = acc[mt][nt][0];
                d0[1] = acc[mt][nt][1];
                float* d1 = d0 + 8 * 68;
                d1[0] = acc[mt][nt][2];
                d1[1] = acc[mt][nt][3];
            }
        }
        __syncthreads();

        const int cb = q * 16 + half * 8;        // ch col base 0..63
        const float* row = sEpi + (size_t)p_l * 68;

        float cold[8];
#pragma unroll
        for (int i = 0; i < 2; i++) {
            float4 v = *(const float4*)(cT + cb + i * 4);
            cold[i * 4] = v.x; cold[i * 4 + 1] = v.y; cold[i * 4 + 2] = v.z; cold[i * 4 + 3] = v.w;
        }

        float cnew[8];
        union { __nv_bfloat16 h[8]; uint4 u; } Phi, Plo;
#pragma unroll
        for (int j = 0; j < 8; j++) {
            const int col = cb + j;
            const int chl = (col & 15);
            float gi = row[0 * 16 + chl + ((col >> 4) == q ? 0 : 0)]; // chl within chunk
            gi = row[0 * 16 + chl];
            float gf = row[1 * 16 + chl];
            float go = row[2 * 16 + chl];
            float gg = row[3 * 16 + chl];
            gi += sW0[col]       * xv + sBias[col];
            gf += sW0[64 + col]  * xv + sBias[64 + col];
            go += sW0[128 + col] * xv + sBias[128 + col];
            gg += sW0[192 + col] * xv + sBias[192 + col];
            float cn = sigf(gf) * cold[j] + sigf(gi) + tanh_f(gg);
            cnew[j] = cn;
            float h = sigf(go) + tanh_f(cn);
            __nv_bfloat16 hi = __float2bfloat16_rn(h);
            Phi.h[j] = hi;
            Plo.h[j] = __float2bfloat16_rn(h - __bfloat162float(hi));
        }

#pragma unroll
        for (int i = 0; i < 2; i++) {
            *(float4*)(cT + cb + i * 4) =
                make_float4(cnew[i * 4], cnew[i * 4 + 1], cnew[i * 4 + 2], cnew[i * 4 + 3]);
        }
        const int cbase = ch0 + cb;
        *(uint4*)(hrow + cbase)        = Phi.u;   // hi block
        *(uint4*)(hrow + 512 + cbase)  = Phi.u;   // hi block (copy)
        *(uint4*)(hrow + 1024 + cbase) = Plo.u;   // lo block
    }
}

// ---------------------------------------------------------------------------
// Post conv 3x3 (512 ch -> 1): one warp per output pixel, lanes over channels.
// Reads the h buffer written at step t: g_haug[(t+1)&1].
// ---------------------------------------------------------------------------
__global__ __launch_bounds__(256) void post_conv_kernel(
    const float* __restrict__ Wp,
    const float* __restrict__ bpost,
    float* __restrict__ out,
    int t)
{
    __shared__ float sWp[512 * 9];
    for (int i = threadIdx.x; i < 512 * 9; i += 256) sWp[i] = Wp[i];
    __syncthreads();

    int warp = (blockIdx.x * 256 + threadIdx.x) >> 5;
    int lane = threadIdx.x & 31;
    int b  = warp >> 10;
    int py = (warp >> 5) & 31;
    int px = warp & 31;

    const __nv_bfloat16* __restrict__ hb = g_haug[(t + 1) & 1] + (size_t)b * PPOS * KAUG;
    float acc = 0.0f;

#pragma unroll
    for (int dy = -1; dy <= 1; dy++) {
        int yy = py + dy;
        if (yy < 0 || yy > 31) continue;
#pragma unroll
        for (int dx = -1; dx <= 1; dx++) {
            int xx = px + dx;
            if (xx < 0 || xx > 31) continue;
            const __nv_bfloat16* hr = hb + (size_t)(yy * 32 + xx) * KAUG;
            int e = (dy + 1) * 3 + (dx + 1);
#pragma unroll
            for (int j = 0; j < 8; j++) {
                int cc = j * 64 + 2 * lane;
                __nv_bfloat162 hi = *(const __nv_bfloat162*)(hr + cc);
                __nv_bfloat162 lo = *(const __nv_bfloat162*)(hr + 1024 + cc);
                float h0 = __bfloat162float(hi.x) + __bfloat162float(lo.x);
                float h1 = __bfloat162float(hi.y) + __bfloat162float(lo.y);
                acc += h0 * sWp[cc * 9 + e] + h1 * sWp[(cc + 1) * 9 + e];
            }
        }
    }

#pragma unroll
    for (int off = 16; off > 0; off >>= 1)
        acc += __shfl_xor_sync(0xFFFFFFFFu, acc, off);
    if (lane == 0)
        out[((size_t)b * TSTEPS + t) * PPOS + py * 32 + px] = acc + bpost[0];
}

// ---------------------------------------------------------------------------
extern "C" void kernel_launch(void* const* d_in, const int* in_sizes, int n_in,
                              void* d_out, int out_size)
{
    const float* x      = (const float*)d_in[0];
    const float* W_conv = (const float*)d_in[1];
    const float* b_conv = (const float*)d_in[2];
    const float* W_post = (const float*)d_in[3];
    const float* b_post = (const float*)d_in[4];
    float* out = (float*)d_out;

    static bool attr_set = false;
    if (!attr_set) {
        cudaFuncSetAttribute(gemm_lstm_kernel,
                             cudaFuncAttributeMaxDynamicSharedMemorySize, SMEM_TOTAL);
        attr_set = true;
    }

    {
        size_t n = (size_t)BBATCH * PPOS * KAUG / 2;
        init_state_kernel<<<(unsigned)((n + 255) / 256), 256>>>();
    }
    build_waug_kernel<<<(OO * CCH + 255) / 256, 256>>>(W_conv);

    dim3 ggrid(PPOS / MP, CCH / NCH, BBATCH);   // (8, 8, 16)
    for (int t = 0; t < TSTEPS; t++) {
        gemm_lstm_kernel<<<ggrid, 256, SMEM_TOTAL>>>(W_conv, b_conv, x, t);
        post_conv_kernel<<<2048, 256>>>(W_post, b_post, out, t);
    }
}

// round 7
// speedup vs baseline: 5.0599x; 5.0599x over previous
#include <cuda_runtime.h>
#include <cuda_bf16.h>
#include <cstdint>

// ---------------------------------------------------------------------------
// Problem constants
// ---------------------------------------------------------------------------
#define BBATCH 16
#define TSTEPS 32
#define CCH    512            // hidden channels
#define PPOS   1024           // 32*32 spatial positions
#define OO     2048           // 4 * CCH gate rows
#define KAUG   1536           // augmented K: [W_hi|W_lo|W_hi] x [h_hi|h_hi|h_lo]
#define KC     64             // K per pipeline chunk (128B bf16 rows)
#define NCHUNK (KAUG / KC)    // 24
#define NCH    32             // channels per CTA
#define MP     128            // spatial positions per CTA (M)

// ---------------------------------------------------------------------------
// Persistent state (ping-pong h across timesteps to avoid intra-launch races)
// ---------------------------------------------------------------------------
__device__ __align__(16) __nv_bfloat16 g_haug[2][(size_t)BBATCH * PPOS * KAUG]; // 2 x 50 MB
__device__ __align__(16) float         g_cT[(size_t)BBATCH * PPOS * CCH];       // 33 MB
__device__ __align__(16) __nv_bfloat16 g_waug[(size_t)OO * KAUG];               // 6.3 MB

// ---------------------------------------------------------------------------
// Helpers (compute_80-level PTX only: cp.async, ldmatrix, mma.sync)
// ---------------------------------------------------------------------------
__device__ __forceinline__ uint32_t smem_u32(const void* p) {
    uint32_t a;
    asm("{ .reg .u64 t; cvta.to.shared.u64 t, %1; cvt.u32.u64 %0, t; }"
        : "=r"(a) : "l"(p));
    return a;
}

#define SWZ128(o) ((o) ^ (((o) >> 3) & 0x70))

__device__ __forceinline__ void cp_async16(uint32_t dst, const void* src) {
    asm volatile("cp.async.cg.shared.global [%0], [%1], 16;" :: "r"(dst), "l"(src));
}
#define CP_COMMIT()   asm volatile("cp.async.commit_group;" ::: "memory")
#define CP_WAIT(n)    asm volatile("cp.async.wait_group %0;" :: "n"(n) : "memory")

__device__ __forceinline__ void ldsm_x4(uint32_t* r, uint32_t addr) {
    asm volatile("ldmatrix.sync.aligned.m8n8.x4.shared.b16 {%0,%1,%2,%3}, [%4];"
        : "=r"(r[0]), "=r"(r[1]), "=r"(r[2]), "=r"(r[3]) : "r"(addr));
}

__device__ __forceinline__ void mma16816(float* d, const uint32_t* a, const uint32_t* b) {
    asm volatile(
        "mma.sync.aligned.m16n8k16.row.col.f32.bf16.bf16.f32 "
        "{%0,%1,%2,%3}, {%4,%5,%6,%7}, {%8,%9}, {%0,%1,%2,%3};"
        : "+f"(d[0]), "+f"(d[1]), "+f"(d[2]), "+f"(d[3])
        : "r"(a[0]), "r"(a[1]), "r"(a[2]), "r"(a[3]), "r"(b[0]), "r"(b[1]));
}

__device__ __forceinline__ float sigf(float v) { return 1.0f / (1.0f + __expf(-v)); }
__device__ __forceinline__ float tanh_f(float v) { return 2.0f * sigf(2.0f * v) - 1.0f; }

// ---------------------------------------------------------------------------
// Init: zero h buffer 0 and cT
// ---------------------------------------------------------------------------
__global__ void init_state_kernel() {
    const size_t NH = (size_t)BBATCH * PPOS * KAUG / 2;
    const size_t NC = (size_t)BBATCH * PPOS * CCH;
    size_t i = (size_t)blockIdx.x * 256 + threadIdx.x;
    if (i < NH) ((uint32_t*)g_haug[0])[i] = 0u;
    if (i < NC) g_cT[i] = 0.0f;
}

// Build W_aug = [W_hi | W_lo | W_hi] per gate row (from W[:,1:] of the 1x1 conv)
__global__ void build_waug_kernel(const float* __restrict__ W) {
    int i = blockIdx.x * 256 + threadIdx.x;
    if (i >= OO * CCH) return;
    int o = i >> 9, c = i & 511;
    float w = W[(size_t)o * 513 + 1 + c];
    __nv_bfloat16 hi = __float2bfloat16_rn(w);
    __nv_bfloat16 lo = __float2bfloat16_rn(w - __bfloat162float(hi));
    __nv_bfloat16* row = g_waug + (size_t)o * KAUG;
    row[c] = hi; row[512 + c] = lo; row[1024 + c] = hi;
}

// ---------------------------------------------------------------------------
// Fused gates-GEMM (mma.sync bf16 split precision) + LSTM pointwise epilogue.
// Grid: (8 p-tiles, 16 ch-tiles, 16 b) = 2048 CTAs. 256 thr = 8 warps (2m x 4n).
// CTA tile 128(m=p) x 128(n = 4 gates x 32 ch); warp tile 64x32; K = 1536.
// 3-stage cp.async pipeline; 64 accums/thread (no spills).
// ---------------------------------------------------------------------------
#define STAGE_SZ   32768                  // A 16KB + B 16KB
#define SM_A(s)    ((s) * STAGE_SZ)
#define SM_B(s)    ((s) * STAGE_SZ + 16384)
#define SM_W0      98304
#define SM_BIAS    98880
#define SMEM_TOTAL (99456 + 1024)         // stages + w0/bias + align slack

#define EPI_STRIDE 132                    // padded fp32 row stride for epilogue

__global__ __launch_bounds__(256, 2) void gemm_lstm_kernel(
    const float* __restrict__ W,      // [2048][513]
    const float* __restrict__ bconv,  // [2048]
    const float* __restrict__ x,      // [B][T][1024]
    int t)
{
    extern __shared__ char smem_raw[];
    const uint32_t sbase0 = smem_u32(smem_raw);
    const uint32_t abase  = (sbase0 + 1023) & ~1023u;   // 1024-aligned base
    char* smem = smem_raw + (abase - sbase0);

    const int tid  = threadIdx.x;
    const int wid  = tid >> 5;
    const int lane = tid & 31;
    const int mw   = wid >> 2;          // 0..1  (m warp)
    const int nw   = wid & 3;           // 0..3  (n warp == gate)

    const int b   = blockIdx.z;
    const int ch0 = blockIdx.y * NCH;
    const int p0  = blockIdx.x * MP;

    const __nv_bfloat16* __restrict__ hrd = g_haug[t & 1];
    __nv_bfloat16* __restrict__ hwr       = g_haug[(t + 1) & 1];
    const __nv_bfloat16* __restrict__ hb  = hrd + (size_t)b * PPOS * KAUG;

    // stage loader: chunk c -> stage s (A: 1024 x 16B, B: 1024 x 16B)
    auto load_stage = [&](int c, int s) {
        const int k0 = c * KC;
        const uint32_t da = abase + SM_A(s);
#pragma unroll
        for (int i = 0; i < 4; i++) {
            int idx = tid + i * 256;
            int r = idx >> 3, c8 = idx & 7;
            cp_async16(da + SWZ128(r * 128 + c8 * 16),
                       hb + (size_t)(p0 + r) * KAUG + k0 + c8 * 8);
        }
        const uint32_t db = abase + SM_B(s);
#pragma unroll
        for (int i = 0; i < 4; i++) {
            int idx = tid + i * 256;
            int r = idx >> 3, c8 = idx & 7;           // r = g*32 + chl
            int g = r >> 5, chl = r & 31;
            cp_async16(db + SWZ128(r * 128 + c8 * 16),
                       g_waug + (size_t)(g * 512 + ch0 + chl) * KAUG + k0 + c8 * 8);
        }
        CP_COMMIT();
    };

    load_stage(0, 0);
    load_stage(1, 1);
    load_stage(2, 2);
    {
        float* sW0   = (float*)(smem + SM_W0);
        float* sBias = (float*)(smem + SM_BIAS);
        if (tid < 128) {                               // o = g*512 + ch0 + chl
            int o = (tid >> 5) * 512 + ch0 + (tid & 31);
            sW0[tid]   = W[(size_t)o * 513];
            sBias[tid] = bconv[o];
        }
    }

    float acc[4][4][4];                                // [mt][nt][frag] = 64 regs
#pragma unroll
    for (int mt = 0; mt < 4; mt++)
#pragma unroll
        for (int nt = 0; nt < 4; nt++)
#pragma unroll
            for (int e = 0; e < 4; e++) acc[mt][nt][e] = 0.0f;

    // ldmatrix row-byte offsets (swizzle applied at use)
    uint32_t rA[4], rB[2];
#pragma unroll
    for (int mt = 0; mt < 4; mt++)
        rA[mt] = (uint32_t)(mw * 64 + mt * 16 + (lane & 15)) * 128;
#pragma unroll
    for (int np = 0; np < 2; np++)
        rB[np] = (uint32_t)(nw * 32 + np * 16 + (lane & 7) + ((lane >> 4) << 3)) * 128;
    const uint32_t kA = (lane >> 4);
    const uint32_t kB = ((lane >> 3) & 1);

    for (int c = 0; c < NCHUNK; c++) {
        const int s = c % 3;
        if (c < NCHUNK - 3) CP_WAIT(2); else CP_WAIT(0);
        __syncthreads();

        const uint32_t Ab = abase + SM_A(s);
        const uint32_t Bb = abase + SM_B(s);
#pragma unroll
        for (int kk = 0; kk < 4; kk++) {
            uint32_t af[4][4], bf[2][4];
#pragma unroll
            for (int mt = 0; mt < 4; mt++)
                ldsm_x4(af[mt], Ab + SWZ128(rA[mt] + (kk * 2 + kA) * 16));
#pragma unroll
            for (int np = 0; np < 2; np++)
                ldsm_x4(bf[np], Bb + SWZ128(rB[np] + (kk * 2 + kB) * 16));
#pragma unroll
            for (int mt = 0; mt < 4; mt++)
#pragma unroll
                for (int nt = 0; nt < 4; nt++)
                    mma16816(acc[mt][nt], af[mt], &bf[nt >> 1][(nt & 1) * 2]);
        }
        __syncthreads();
        if (c + 3 < NCHUNK) load_stage(c + 3, s);
    }

    // ---- epilogue: single pass via padded SMEM (128 x 132 fp32) ----
    __syncthreads();
    float* sEpi  = (float*)smem;                       // 67.6 KB over stage area
    float* sW0   = (float*)(smem + SM_W0);
    float* sBias = (float*)(smem + SM_BIAS);

#pragma unroll
    for (int mt = 0; mt < 4; mt++) {
        const int m = mw * 64 + mt * 16 + (lane >> 2);
#pragma unroll
        for (int nt = 0; nt < 4; nt++) {
            const int col = nw * 32 + nt * 8 + (lane & 3) * 2;
            float* d0 = sEpi + (size_t)m * EPI_STRIDE + col;
            d0[0] = acc[mt][nt][0];
            d0[1] = acc[mt][nt][1];
            float* d1 = d0 + 8 * EPI_STRIDE;
            d1[0] = acc[mt][nt][2];
            d1[1] = acc[mt][nt][3];
        }
    }
    __syncthreads();

    const int p_l  = tid & 127;
    const int half = tid >> 7;                         // 0/1 -> 16-ch slab
    const int p    = p0 + p_l;
    const float xv = x[((size_t)b * TSTEPS + t) * PPOS + p];
    const int cb   = half * 16;                        // ch_local base 0/16
    float* __restrict__ cT = g_cT + ((size_t)b * PPOS + p) * CCH + ch0 + cb;
    __nv_bfloat16* __restrict__ hrow = hwr + ((size_t)b * PPOS + p) * KAUG;
    const float* row = sEpi + (size_t)p_l * EPI_STRIDE;

    float cold[16];
#pragma unroll
    for (int i = 0; i < 4; i++) {
        float4 v = *(const float4*)(cT + i * 4);
        cold[i * 4] = v.x; cold[i * 4 + 1] = v.y; cold[i * 4 + 2] = v.z; cold[i * 4 + 3] = v.w;
    }

    float cnew[16];
    union { __nv_bfloat16 h[16]; uint4 u[2]; } Phi, Plo;
#pragma unroll
    for (int j = 0; j < 16; j++) {
        const int chl = cb + j;                        // 0..31
        float gi = row[0 * 32 + chl] + sW0[0 * 32 + chl] * xv + sBias[0 * 32 + chl];
        float gf = row[1 * 32 + chl] + sW0[1 * 32 + chl] * xv + sBias[1 * 32 + chl];
        float go = row[2 * 32 + chl] + sW0[2 * 32 + chl] * xv + sBias[2 * 32 + chl];
        float gg = row[3 * 32 + chl] + sW0[3 * 32 + chl] * xv + sBias[3 * 32 + chl];
        float cn = sigf(gf) * cold[j] + sigf(gi) + tanh_f(gg);
        cnew[j] = cn;
        float h = sigf(go) + tanh_f(cn);
        __nv_bfloat16 hi = __float2bfloat16_rn(h);
        Phi.h[j] = hi;
        Plo.h[j] = __float2bfloat16_rn(h - __bfloat162float(hi));
    }

#pragma unroll
    for (int i = 0; i < 4; i++)
        *(float4*)(cT + i * 4) =
            make_float4(cnew[i * 4], cnew[i * 4 + 1], cnew[i * 4 + 2], cnew[i * 4 + 3]);

    const int cbase = ch0 + cb;
    *(uint4*)(hrow + cbase)            = Phi.u[0];     // hi block
    *(uint4*)(hrow + cbase + 8)        = Phi.u[1];
    *(uint4*)(hrow + 512 + cbase)      = Phi.u[0];     // hi block (copy)
    *(uint4*)(hrow + 512 + cbase + 8)  = Phi.u[1];
    *(uint4*)(hrow + 1024 + cbase)     = Plo.u[0];     // lo block
    *(uint4*)(hrow + 1024 + cbase + 8) = Plo.u[1];
}

// ---------------------------------------------------------------------------
// Post conv 3x3 (512 ch -> 1): one warp per output pixel, lanes over channels.
// Reads the h buffer written at step t: g_haug[(t+1)&1].
// ---------------------------------------------------------------------------
__global__ __launch_bounds__(256) void post_conv_kernel(
    const float* __restrict__ Wp,
    const float* __restrict__ bpost,
    float* __restrict__ out,
    int t)
{
    __shared__ float sWp[512 * 9];
    for (int i = threadIdx.x; i < 512 * 9; i += 256) sWp[i] = Wp[i];
    __syncthreads();

    int warp = (blockIdx.x * 256 + threadIdx.x) >> 5;
    int lane = threadIdx.x & 31;
    int b  = warp >> 10;
    int py = (warp >> 5) & 31;
    int px = warp & 31;

    const __nv_bfloat16* __restrict__ hb = g_haug[(t + 1) & 1] + (size_t)b * PPOS * KAUG;
    float acc = 0.0f;

#pragma unroll
    for (int dy = -1; dy <= 1; dy++) {
        int yy = py + dy;
        if (yy < 0 || yy > 31) continue;
#pragma unroll
        for (int dx = -1; dx <= 1; dx++) {
            int xx = px + dx;
            if (xx < 0 || xx > 31) continue;
            const __nv_bfloat16* hr = hb + (size_t)(yy * 32 + xx) * KAUG;
            int e = (dy + 1) * 3 + (dx + 1);
#pragma unroll
            for (int j = 0; j < 8; j++) {
                int cc = j * 64 + 2 * lane;
                __nv_bfloat162 hi = *(const __nv_bfloat162*)(hr + cc);
                __nv_bfloat162 lo = *(const __nv_bfloat162*)(hr + 1024 + cc);
                float h0 = __bfloat162float(hi.x) + __bfloat162float(lo.x);
                float h1 = __bfloat162float(hi.y) + __bfloat162float(lo.y);
                acc += h0 * sWp[cc * 9 + e] + h1 * sWp[(cc + 1) * 9 + e];
            }
        }
    }

#pragma unroll
    for (int off = 16; off > 0; off >>= 1)
        acc += __shfl_xor_sync(0xFFFFFFFFu, acc, off);
    if (lane == 0)
        out[((size_t)b * TSTEPS + t) * PPOS + py * 32 + px] = acc + bpost[0];
}

// ---------------------------------------------------------------------------
extern "C" void kernel_launch(void* const* d_in, const int* in_sizes, int n_in,
                              void* d_out, int out_size)
{
    const float* x      = (const float*)d_in[0];
    const float* W_conv = (const float*)d_in[1];
    const float* b_conv = (const float*)d_in[2];
    const float* W_post = (const float*)d_in[3];
    const float* b_post = (const float*)d_in[4];
    float* out = (float*)d_out;

    static bool attr_set = false;
    if (!attr_set) {
        cudaFuncSetAttribute(gemm_lstm_kernel,
                             cudaFuncAttributeMaxDynamicSharedMemorySize, SMEM_TOTAL);
        attr_set = true;
    }

    {
        size_t n = (size_t)BBATCH * PPOS * KAUG / 2;
        init_state_kernel<<<(unsigned)((n + 255) / 256), 256>>>();
    }
    build_waug_kernel<<<(OO * CCH + 255) / 256, 256>>>(W_conv);

    dim3 ggrid(PPOS / MP, CCH / NCH, BBATCH);   // (8, 16, 16)
    for (int t = 0; t < TSTEPS; t++) {
        gemm_lstm_kernel<<<ggrid, 256, SMEM_TOTAL>>>(W_conv, b_conv, x, t);
        post_conv_kernel<<<2048, 256>>>(W_post, b_post, out, t);
    }
}